// round 4
// baseline (speedup 1.0000x reference)
#include <cuda_runtime.h>
#include <cstdint>
#include <cstddef>

#define NE   100000
#define NNZ  500000
#define EPS  1e-5f

// ---------------- scratch (static device allocations) ----------------
// pair p = 2*r + side; entity of pair: {0,1,1,2,0,2}
__device__ __align__(256) int   g_deg[6][NE];          // degrees per (rel,side)
__device__ __align__(256) float g_ss16[6][NE][16];     // stage-1 segment sums
__device__ __align__(256) float g_ss64[6][NE][64];     // stage-2 segment sums (slots 0,4 reused stage-3)
__device__ __align__(256) float g_emb[3][NE][64];      // pre-BN entity activations (reused layer 2)
__device__ __align__(256) float g_P[6][NE][64];        // per-entity bcast tables (reused for layer 2)
__device__ __align__(256) float g_bnacc[3][2][64];     // BN partial sums (sum, sumsq)
__device__ __align__(256) float g_bn[3][2][64];        // BN (mu, inv_sigma)

struct EdgePtrs {
    const float* vals[3];
    const int*   row[3];
    const int*   col[3];
};

__device__ __forceinline__ void red_add_v4(float* p, float4 v) {
    asm volatile("red.global.add.v4.f32 [%0], {%1,%2,%3,%4};"
                 :: "l"(p), "f"(v.x), "f"(v.y), "f"(v.z), "f"(v.w) : "memory");
}

// ---------------- zeroing ----------------
__global__ void k_zeroA() {
    const float4 z = make_float4(0.f, 0.f, 0.f, 0.f);
    size_t t  = (size_t)blockIdx.x * blockDim.x + threadIdx.x;
    size_t st = (size_t)gridDim.x * blockDim.x;
    float4* a = (float4*)&g_ss64[0][0][0];
    for (size_t i = t; i < (size_t)6 * NE * 16; i += st) a[i] = z;
    float4* b = (float4*)&g_ss16[0][0][0];
    for (size_t i = t; i < (size_t)6 * NE * 4; i += st) b[i] = z;
    int4 zi = {0, 0, 0, 0};
    int4* d = (int4*)&g_deg[0][0];
    for (size_t i = t; i < (size_t)6 * NE / 4; i += st) d[i] = zi;
    if (t < 384) ((float*)g_bnacc)[t] = 0.f;
}

__global__ void k_zeroB() {  // re-zero ss64 slots 0 and 4 for final pool
    const float4 z = make_float4(0.f, 0.f, 0.f, 0.f);
    size_t t  = (size_t)blockIdx.x * blockDim.x + threadIdx.x;
    size_t st = (size_t)gridDim.x * blockDim.x;
    float4* a = (float4*)&g_ss64[0][0][0];
    float4* b = (float4*)&g_ss64[4][0][0];
    for (size_t i = t; i < (size_t)NE * 16; i += st) { a[i] = z; b[i] = z; }
}

// ---------------- stage-1 segment sums of raw values (16 ch) + degrees ----------------
__global__ __launch_bounds__(256) void k_ss16(EdgePtrs ep) {
    int r = blockIdx.y;
    const float* vp = ep.vals[r];
    const int* rw = ep.row[r];
    const int* cl = ep.col[r];
    for (size_t t = (size_t)blockIdx.x * 256 + threadIdx.x; t < (size_t)NNZ * 4;
         t += (size_t)gridDim.x * 256) {
        int e = (int)(t >> 2);
        int g = (int)(t & 3);
        int c = g * 4;
        float4 v = __ldg((const float4*)(vp + (size_t)e * 16 + c));
        int ri = __ldg(rw + e), ci = __ldg(cl + e);
        if (g == 0) {  // fused degree count: one lane-group per edge
            atomicAdd(&g_deg[2 * r][ri], 1);
            atomicAdd(&g_deg[2 * r + 1][ci], 1);
        }
        red_add_v4(&g_ss16[2 * r][ri][c], v);
        red_add_v4(&g_ss16[2 * r + 1][ci][c], v);
    }
}

// ---------------- entity stage: mean -> dual matmul -> relu -> BN stats ----------------
// pw layout [3][2][C][64]; entity e pulls pairs PA[e], PB[e].
template <int C>
__global__ __launch_bounds__(256) void k_entity(const float* __restrict__ pw) {
    const int PA_[3] = {0, 1, 3}, PB_[3] = {4, 2, 5};
    int e = blockIdx.y;
    int pa = PA_[e], pb = PB_[e];
    __shared__ float sW[2 * C * 64];
    for (int i = threadIdx.x; i < 2 * C * 64; i += 256)
        sW[i] = (i < C * 64) ? __ldg(pw + pa * C * 64 + i)
                             : __ldg(pw + pb * C * 64 + i - C * 64);
    __shared__ float sIn[4][2 * C + 4];
    __shared__ float red[256];
    int o = threadIdx.x & 63, rg = threadIdx.x >> 6;
    const float *ssA, *ssB;
    if (C == 16) { ssA = &g_ss16[pa][0][0]; ssB = &g_ss16[pb][0][0]; }
    else         { ssA = &g_ss64[pa][0][0]; ssB = &g_ss64[pb][0][0]; }
    const int* dgA = &g_deg[pa][0];
    const int* dgB = &g_deg[pb][0];
    float sx = 0.f, sxx = 0.f;
    for (int i0 = blockIdx.x * 4; i0 < NE; i0 += gridDim.x * 4) {
        int i = i0 + rg;
        __syncthreads();
        if (i < NE) {
            float invA = 1.0f / (float)max(__ldg(dgA + i), 1);
            float invB = 1.0f / (float)max(__ldg(dgB + i), 1);
            for (int j = o; j < 2 * C; j += 64)
                sIn[rg][j] = (j < C) ? __ldg(ssA + (size_t)i * C + j) * invA
                                     : __ldg(ssB + (size_t)i * C + j - C) * invB;
        }
        __syncthreads();
        if (i < NE) {
            float acc = 0.f;
#pragma unroll
            for (int j = 0; j < 2 * C; j++) acc = fmaf(sIn[rg][j], sW[j * 64 + o], acc);
            float x = fmaxf(acc, 0.f);
            g_emb[e][i][o] = x;
            sx += x;
            sxx += x * x;
        }
    }
    red[threadIdx.x] = sx;
    __syncthreads();
    if (threadIdx.x < 64)
        atomicAdd(&g_bnacc[e][0][o], red[o] + red[o + 64] + red[o + 128] + red[o + 192]);
    __syncthreads();
    red[threadIdx.x] = sxx;
    __syncthreads();
    if (threadIdx.x < 64)
        atomicAdd(&g_bnacc[e][1][o], red[o] + red[o + 64] + red[o + 128] + red[o + 192]);
}

// ---------------- BN finalize (and reset accumulators) ----------------
__global__ void k_bnfin() {
    int t = threadIdx.x;
    if (t >= 192) return;
    int e = t / 64, c = t % 64;
    float s = g_bnacc[e][0][c], q = g_bnacc[e][1][c];
    float mu = s / (float)NE;
    float var = fmaxf(q / (float)NE - mu * mu, 0.f);
    g_bn[e][0][c] = mu;
    g_bn[e][1][c] = rsqrtf(var + EPS);
    g_bnacc[e][0][c] = 0.f;
    g_bnacc[e][1][c] = 0.f;
}

// ---------------- per-entity bcast tables: P[p] = BN(emb[e]) @ bw[p] ----------------
__global__ __launch_bounds__(256) void k_bcastW(const float* __restrict__ bw, int qmode) {
    const int EM[6] = {0, 1, 1, 2, 0, 2};
    const int QM[4] = {0, 1, 4, 5};
    int p = qmode ? QM[blockIdx.y] : (int)blockIdx.y;
    int e = EM[p];
    __shared__ float sW[4096];
    for (int i = threadIdx.x; i < 4096; i += 256) sW[i] = __ldg(bw + p * 4096 + i);
    __shared__ float sIn[4][68];
    int o = threadIdx.x & 63, rg = threadIdx.x >> 6;
    float mu = g_bn[e][0][o], is = g_bn[e][1][o];
    for (int i0 = blockIdx.x * 4; i0 < NE; i0 += gridDim.x * 4) {
        int i = i0 + rg;
        __syncthreads();
        if (i < NE) sIn[rg][o] = (g_emb[e][i][o] - mu) * is;
        __syncthreads();
        if (i < NE) {
            float acc = 0.f;
#pragma unroll
            for (int j = 0; j < 64; j++) acc = fmaf(sIn[rg][j], sW[j * 64 + o], acc);
            g_P[p][i][o] = acc;
        }
    }
}

// ---------------- edge pass: gather + relu(sum) + scatter-reduce ----------------
// One thread per (edge, quarter): thread owns 16 consecutive channels (4 x float4),
// loading the edge indices once and issuing 4 independent gather/red chains (MLP~8).
__global__ __launch_bounds__(256) void k_edge(EdgePtrs ep, int stage3) {
    int r = stage3 ? (blockIdx.y ? 2 : 0) : (int)blockIdx.y;
    const float* __restrict__ P0 = &g_P[2 * r][0][0];
    const float* __restrict__ P1 = &g_P[2 * r + 1][0][0];
    float* __restrict__ S0 = &g_ss64[2 * r][0][0];
    float* __restrict__ S1 = &g_ss64[2 * r + 1][0][0];
    const int* __restrict__ rw = ep.row[r];
    const int* __restrict__ cl = ep.col[r];
    for (size_t t = (size_t)blockIdx.x * 256 + threadIdx.x; t < (size_t)NNZ * 4;
         t += (size_t)gridDim.x * 256) {
        int e = (int)(t >> 2);
        int c0 = (int)(t & 3) * 16;   // 16-channel slice of the 64-wide row
        int ri = __ldg(rw + e), ci = __ldg(cl + e);
        const float* a0 = P0 + (size_t)ri * 64 + c0;
        const float* b0 = P1 + (size_t)ci * 64 + c0;
        float4 a[4], b[4];
#pragma unroll
        for (int q = 0; q < 4; q++) a[q] = __ldg((const float4*)(a0 + q * 4));
#pragma unroll
        for (int q = 0; q < 4; q++) b[q] = __ldg((const float4*)(b0 + q * 4));
        float* s0 = S0 + (size_t)ri * 64 + c0;
        float* s1 = S1 + (size_t)ci * 64 + c0;
#pragma unroll
        for (int q = 0; q < 4; q++) {
            float4 s;
            s.x = fmaxf(a[q].x + b[q].x, 0.f);
            s.y = fmaxf(a[q].y + b[q].y, 0.f);
            s.z = fmaxf(a[q].z + b[q].z, 0.f);
            s.w = fmaxf(a[q].w + b[q].w, 0.f);
            red_add_v4(s0 + q * 4, s);
            if (!stage3) red_add_v4(s1 + q * 4, s);
        }
    }
}

// ---------------- final: out = mean0 @ pw2[0,0] + mean2 @ pw2[2,0] ----------------
__global__ __launch_bounds__(256) void k_out(const float* __restrict__ pw2,
                                             float* __restrict__ out) {
    __shared__ float sW[2048];  // pair 0 (r0,row) then pair 4 (r2,row), each 64x16
    for (int i = threadIdx.x; i < 2048; i += 256)
        sW[i] = (i < 1024) ? __ldg(pw2 + i) : __ldg(pw2 + 4 * 1024 + i - 1024);
    __shared__ float sIn[16][132];
    int o = threadIdx.x & 15, rg = threadIdx.x >> 4;
    for (int i0 = blockIdx.x * 16; i0 < NE; i0 += gridDim.x * 16) {
        int i = i0 + rg;
        __syncthreads();
        if (i < NE) {
            float inv0 = 1.0f / (float)max(g_deg[0][i], 1);
            float inv4 = 1.0f / (float)max(g_deg[4][i], 1);
            for (int j = o; j < 128; j += 16)
                sIn[rg][j] = (j < 64) ? g_ss64[0][i][j] * inv0
                                      : g_ss64[4][i][j - 64] * inv4;
        }
        __syncthreads();
        if (i < NE) {
            float acc = 0.f;
#pragma unroll
            for (int j = 0; j < 128; j++) acc = fmaf(sIn[rg][j], sW[j * 16 + o], acc);
            out[i * 16 + o] = acc;
        }
    }
}

// ---------------- launch ----------------
extern "C" void kernel_launch(void* const* d_in, const int* in_sizes, int n_in,
                              void* d_out, int out_size) {
    EdgePtrs ep;
    if (in_sizes[1] == NNZ) {
        // insertion order: vals0,row0,col0,vals1,row1,col1,vals2,row2,col2
        for (int r = 0; r < 3; r++) {
            ep.vals[r] = (const float*)d_in[3 * r];
            ep.row[r]  = (const int*)d_in[3 * r + 1];
            ep.col[r]  = (const int*)d_in[3 * r + 2];
        }
    } else {
        // signature order: vals0,vals1,vals2,row0,col0,row1,col1,row2,col2
        for (int r = 0; r < 3; r++) {
            ep.vals[r] = (const float*)d_in[r];
            ep.row[r]  = (const int*)d_in[3 + 2 * r];
            ep.col[r]  = (const int*)d_in[4 + 2 * r];
        }
    }
    const float* pw0 = (const float*)d_in[9];
    const float* pw1 = (const float*)d_in[10];
    const float* pw2 = (const float*)d_in[11];
    const float* bw0 = (const float*)d_in[12];
    const float* bw1 = (const float*)d_in[13];
    float* out = (float*)d_out;

    k_zeroA<<<4096, 256>>>();
    k_ss16<<<dim3(4096, 3), 256>>>(ep);
    k_entity<16><<<dim3(1024, 3), 256>>>(pw0);
    k_bnfin<<<1, 192>>>();
    k_bcastW<<<dim3(1024, 6), 256>>>(bw0, 0);
    k_edge<<<dim3(4096, 3), 256>>>(ep, 0);
    k_entity<64><<<dim3(1024, 3), 256>>>(pw1);
    k_bnfin<<<1, 192>>>();
    k_zeroB<<<2048, 256>>>();
    k_bcastW<<<dim3(1024, 4), 256>>>(bw1, 1);
    k_edge<<<dim3(4096, 2), 256>>>(ep, 1);
    k_out<<<1024, 256>>>(pw2, out);
}

// round 9
// speedup vs baseline: 1.0612x; 1.0612x over previous
#include <cuda_runtime.h>
#include <cstdint>
#include <cstddef>

#define NE   100000
#define NNZ  500000
#define EPS  1e-5f

// pair p = 2*r + side; entity of pair: {0,1,1,2,0,2}
__device__ __align__(256) int   g_deg[6][NE];        // degrees per (rel,side)
__device__ __align__(256) int   g_rowptr[6][NE];     // CSR row starts
__device__ __align__(256) int   g_cursor[6][NE];     // fill cursors
__device__ __align__(256) int2  g_adj[6][NNZ];       // {edge id, other endpoint}
__device__ __align__(256) int   g_part[6][128];      // scan block partials
__device__ __align__(256) float g_ss16[6][NE][16];   // stage-1 pooled sums
__device__ __align__(256) float g_ss64[6][NE][64];   // stage-2/3 pooled sums
__device__ __align__(256) float g_emb[3][NE][64];    // pre-BN entity activations
__device__ __align__(256) float g_P[6][NE][64];      // per-entity bcast tables
__device__ __align__(256) float g_bnacc[3][2][64];   // BN partial sums
__device__ __align__(256) float g_bn[3][2][64];      // BN (mu, inv_sigma)

struct EdgePtrs {
    const float* vals[3];
    const int*   row[3];
    const int*   col[3];
};

// ---------------- zero (only deg + bnacc now) ----------------
__global__ void k_zero() {
    size_t t  = (size_t)blockIdx.x * blockDim.x + threadIdx.x;
    size_t st = (size_t)gridDim.x * blockDim.x;
    int4 zi = {0, 0, 0, 0};
    int4* d = (int4*)&g_deg[0][0];
    for (size_t i = t; i < (size_t)6 * NE / 4; i += st) d[i] = zi;
    if (t < 384) ((float*)g_bnacc)[t] = 0.f;
}

// ---------------- degrees ----------------
__global__ void k_deg(EdgePtrs ep) {
    int r = blockIdx.y;
    const int* rw = ep.row[r];
    const int* cl = ep.col[r];
    for (int t = blockIdx.x * blockDim.x + threadIdx.x; t < NNZ;
         t += gridDim.x * blockDim.x) {
        atomicAdd(&g_deg[2 * r][__ldg(rw + t)], 1);
        atomicAdd(&g_deg[2 * r + 1][__ldg(cl + t)], 1);
    }
}

// ---------------- 3-phase exclusive scan of degrees -> rowptr ----------------
__global__ void k_scan1() {
    int p = blockIdx.y, tid = threadIdx.x;
    int base = blockIdx.x * 1024 + tid * 4;
    int s = 0;
#pragma unroll
    for (int q = 0; q < 4; q++) if (base + q < NE) s += g_deg[p][base + q];
    __shared__ int sh[256];
    sh[tid] = s; __syncthreads();
    for (int off = 128; off; off >>= 1) {
        if (tid < off) sh[tid] += sh[tid + off];
        __syncthreads();
    }
    if (tid == 0) g_part[p][blockIdx.x] = sh[0];
}

__global__ void k_scan2() {
    int p = threadIdx.x;
    if (p >= 6) return;
    int acc = 0;
    for (int b = 0; b < 98; b++) { int v = g_part[p][b]; g_part[p][b] = acc; acc += v; }
}

__global__ void k_scan3() {
    int p = blockIdx.y, tid = threadIdx.x;
    int base = blockIdx.x * 1024 + tid * 4;
    int d[4];
    int s = 0;
#pragma unroll
    for (int q = 0; q < 4; q++) {
        d[q] = (base + q < NE) ? g_deg[p][base + q] : 0;
        s += d[q];
    }
    __shared__ int sh[256];
    sh[tid] = s; __syncthreads();
    for (int off = 1; off < 256; off <<= 1) {
        int v = (tid >= off) ? sh[tid - off] : 0;
        __syncthreads();
        sh[tid] += v;
        __syncthreads();
    }
    int run = sh[tid] - s + g_part[p][blockIdx.x];
#pragma unroll
    for (int q = 0; q < 4; q++) {
        if (base + q < NE) {
            g_rowptr[p][base + q] = run;
            g_cursor[p][base + q] = run;
            run += d[q];
        }
    }
}

// ---------------- adjacency fill ----------------
__global__ void k_fill(EdgePtrs ep) {
    int r = blockIdx.y;
    const int* rw = ep.row[r];
    const int* cl = ep.col[r];
    for (int e = blockIdx.x * blockDim.x + threadIdx.x; e < NNZ;
         e += gridDim.x * blockDim.x) {
        int ri = __ldg(rw + e), ci = __ldg(cl + e);
        int pos = atomicAdd(&g_cursor[2 * r][ri], 1);
        g_adj[2 * r][pos] = make_int2(e, ci);
        pos = atomicAdd(&g_cursor[2 * r + 1][ci], 1);
        g_adj[2 * r + 1][pos] = make_int2(e, ri);
    }
}

// ---------------- stage-1 pool: sum vals over adjacency (16 ch) ----------------
__global__ __launch_bounds__(256) void k_pool16(const float* __restrict__ vp, int rel) {
    int p = 2 * rel + blockIdx.y;
    int t = blockIdx.x * 256 + threadIdx.x;
    int i = t >> 2;
    if (i >= NE) return;
    int q = (t & 3) * 4;
    int s = __ldg(&g_rowptr[p][i]), e = s + __ldg(&g_deg[p][i]);
    const int2* __restrict__ adj = &g_adj[p][0];
    float4 acc = make_float4(0.f, 0.f, 0.f, 0.f);
    for (int j = s; j < e; j++) {
        int eid = __ldg((const int*)&adj[j].x);
        float4 v = __ldg((const float4*)(vp + (size_t)eid * 16 + q));
        acc.x += v.x; acc.y += v.y; acc.z += v.z; acc.w += v.w;
    }
    *(float4*)&g_ss16[p][i][q] = acc;
}

// ---------------- stage-2/3 pool: sum relu(P_own[i] + P_other[o]) (64 ch) ----------------
__device__ __forceinline__ void pool64_body(int p, int pother) {
    int t = blockIdx.x * 256 + threadIdx.x;
    int i = t >> 2;
    if (i >= NE) return;
    int q = (t & 3) * 16;
    const float* own = &g_P[p][i][q];
    float4 o0 = __ldg((const float4*)(own + 0));
    float4 o1 = __ldg((const float4*)(own + 4));
    float4 o2 = __ldg((const float4*)(own + 8));
    float4 o3 = __ldg((const float4*)(own + 12));
    float4 a0 = make_float4(0.f, 0.f, 0.f, 0.f), a1 = a0, a2 = a0, a3 = a0;
    int s = __ldg(&g_rowptr[p][i]), e = s + __ldg(&g_deg[p][i]);
    const int2* __restrict__ adj = &g_adj[p][0];
    const float* __restrict__ PO = &g_P[pother][0][0];
    for (int j = s; j < e; j++) {
        int o = __ldg((const int*)&adj[j].y);
        const float* pr = PO + (size_t)o * 64 + q;
        float4 b0 = __ldg((const float4*)(pr + 0));
        float4 b1 = __ldg((const float4*)(pr + 4));
        float4 b2 = __ldg((const float4*)(pr + 8));
        float4 b3 = __ldg((const float4*)(pr + 12));
        a0.x += fmaxf(o0.x + b0.x, 0.f); a0.y += fmaxf(o0.y + b0.y, 0.f);
        a0.z += fmaxf(o0.z + b0.z, 0.f); a0.w += fmaxf(o0.w + b0.w, 0.f);
        a1.x += fmaxf(o1.x + b1.x, 0.f); a1.y += fmaxf(o1.y + b1.y, 0.f);
        a1.z += fmaxf(o1.z + b1.z, 0.f); a1.w += fmaxf(o1.w + b1.w, 0.f);
        a2.x += fmaxf(o2.x + b2.x, 0.f); a2.y += fmaxf(o2.y + b2.y, 0.f);
        a2.z += fmaxf(o2.z + b2.z, 0.f); a2.w += fmaxf(o2.w + b2.w, 0.f);
        a3.x += fmaxf(o3.x + b3.x, 0.f); a3.y += fmaxf(o3.y + b3.y, 0.f);
        a3.z += fmaxf(o3.z + b3.z, 0.f); a3.w += fmaxf(o3.w + b3.w, 0.f);
    }
    float* dst = &g_ss64[p][i][q];
    *(float4*)(dst + 0) = a0;
    *(float4*)(dst + 4) = a1;
    *(float4*)(dst + 8) = a2;
    *(float4*)(dst + 12) = a3;
}

__global__ __launch_bounds__(256) void k_pool64(int rel) {
    int p = 2 * rel + blockIdx.y;
    pool64_body(p, p ^ 1);
}

__global__ __launch_bounds__(256) void k_pool64s3() {  // pairs 0 and 4 only
    int p = blockIdx.y ? 4 : 0;
    pool64_body(p, p ^ 1);
}

// ---------------- entity stage: mean -> dual matmul -> relu -> BN stats ----------------
template <int C>
__global__ __launch_bounds__(256) void k_entity(const float* __restrict__ pw) {
    const int PA_[3] = {0, 1, 3}, PB_[3] = {4, 2, 5};
    int e = blockIdx.y;
    int pa = PA_[e], pb = PB_[e];
    __shared__ float sW[2 * C * 64];
    for (int i = threadIdx.x; i < 2 * C * 64; i += 256)
        sW[i] = (i < C * 64) ? __ldg(pw + pa * C * 64 + i)
                             : __ldg(pw + pb * C * 64 + i - C * 64);
    __shared__ float sIn[4][2 * C + 4];
    __shared__ float red[256];
    int o = threadIdx.x & 63, rg = threadIdx.x >> 6;
    const float *ssA, *ssB;
    if (C == 16) { ssA = &g_ss16[pa][0][0]; ssB = &g_ss16[pb][0][0]; }
    else         { ssA = &g_ss64[pa][0][0]; ssB = &g_ss64[pb][0][0]; }
    const int* dgA = &g_deg[pa][0];
    const int* dgB = &g_deg[pb][0];
    float sx = 0.f, sxx = 0.f;
    for (int i0 = blockIdx.x * 4; i0 < NE; i0 += gridDim.x * 4) {
        int i = i0 + rg;
        __syncthreads();
        if (i < NE) {
            float invA = 1.0f / (float)max(__ldg(dgA + i), 1);
            float invB = 1.0f / (float)max(__ldg(dgB + i), 1);
            for (int j = o; j < 2 * C; j += 64)
                sIn[rg][j] = (j < C) ? __ldg(ssA + (size_t)i * C + j) * invA
                                     : __ldg(ssB + (size_t)i * C + j - C) * invB;
        }
        __syncthreads();
        if (i < NE) {
            float acc = 0.f;
#pragma unroll
            for (int j = 0; j < 2 * C; j++) acc = fmaf(sIn[rg][j], sW[j * 64 + o], acc);
            float x = fmaxf(acc, 0.f);
            g_emb[e][i][o] = x;
            sx += x;
            sxx += x * x;
        }
    }
    red[threadIdx.x] = sx;
    __syncthreads();
    if (threadIdx.x < 64)
        atomicAdd(&g_bnacc[e][0][o], red[o] + red[o + 64] + red[o + 128] + red[o + 192]);
    __syncthreads();
    red[threadIdx.x] = sxx;
    __syncthreads();
    if (threadIdx.x < 64)
        atomicAdd(&g_bnacc[e][1][o], red[o] + red[o + 64] + red[o + 128] + red[o + 192]);
}

// ---------------- BN finalize (and reset accumulators) ----------------
__global__ void k_bnfin() {
    int t = threadIdx.x;
    if (t >= 192) return;
    int e = t / 64, c = t % 64;
    float s = g_bnacc[e][0][c], q = g_bnacc[e][1][c];
    float mu = s / (float)NE;
    float var = fmaxf(q / (float)NE - mu * mu, 0.f);
    g_bn[e][0][c] = mu;
    g_bn[e][1][c] = rsqrtf(var + EPS);
    g_bnacc[e][0][c] = 0.f;
    g_bnacc[e][1][c] = 0.f;
}

// ---------------- per-entity bcast tables: P[p] = BN(emb[e]) @ bw[p] ----------------
__global__ __launch_bounds__(256) void k_bcastW(const float* __restrict__ bw, int qmode) {
    const int EM[6] = {0, 1, 1, 2, 0, 2};
    const int QM[4] = {0, 1, 4, 5};
    int p = qmode ? QM[blockIdx.y] : (int)blockIdx.y;
    int e = EM[p];
    __shared__ float sW[4096];
    for (int i = threadIdx.x; i < 4096; i += 256) sW[i] = __ldg(bw + p * 4096 + i);
    __shared__ float sIn[4][68];
    int o = threadIdx.x & 63, rg = threadIdx.x >> 6;
    float mu = g_bn[e][0][o], is = g_bn[e][1][o];
    for (int i0 = blockIdx.x * 4; i0 < NE; i0 += gridDim.x * 4) {
        int i = i0 + rg;
        __syncthreads();
        if (i < NE) sIn[rg][o] = (g_emb[e][i][o] - mu) * is;
        __syncthreads();
        if (i < NE) {
            float acc = 0.f;
#pragma unroll
            for (int j = 0; j < 64; j++) acc = fmaf(sIn[rg][j], sW[j * 64 + o], acc);
            g_P[p][i][o] = acc;
        }
    }
}

// ---------------- final: out = mean0 @ pw2[0,0] + mean2 @ pw2[2,0] ----------------
__global__ __launch_bounds__(256) void k_out(const float* __restrict__ pw2,
                                             float* __restrict__ out) {
    __shared__ float sW[2048];
    for (int i = threadIdx.x; i < 2048; i += 256)
        sW[i] = (i < 1024) ? __ldg(pw2 + i) : __ldg(pw2 + 4 * 1024 + i - 1024);
    __shared__ float sIn[16][132];
    int o = threadIdx.x & 15, rg = threadIdx.x >> 4;
    for (int i0 = blockIdx.x * 16; i0 < NE; i0 += gridDim.x * 16) {
        int i = i0 + rg;
        __syncthreads();
        if (i < NE) {
            float inv0 = 1.0f / (float)max(g_deg[0][i], 1);
            float inv4 = 1.0f / (float)max(g_deg[4][i], 1);
            for (int j = o; j < 128; j += 16)
                sIn[rg][j] = (j < 64) ? g_ss64[0][i][j] * inv0
                                      : g_ss64[4][i][j - 64] * inv4;
        }
        __syncthreads();
        if (i < NE) {
            float acc = 0.f;
#pragma unroll
            for (int j = 0; j < 128; j++) acc = fmaf(sIn[rg][j], sW[j * 16 + o], acc);
            out[i * 16 + o] = acc;
        }
    }
}

// ---------------- launch ----------------
extern "C" void kernel_launch(void* const* d_in, const int* in_sizes, int n_in,
                              void* d_out, int out_size) {
    EdgePtrs ep;
    if (in_sizes[1] == NNZ) {
        for (int r = 0; r < 3; r++) {
            ep.vals[r] = (const float*)d_in[3 * r];
            ep.row[r]  = (const int*)d_in[3 * r + 1];
            ep.col[r]  = (const int*)d_in[3 * r + 2];
        }
    } else {
        for (int r = 0; r < 3; r++) {
            ep.vals[r] = (const float*)d_in[r];
            ep.row[r]  = (const int*)d_in[3 + 2 * r];
            ep.col[r]  = (const int*)d_in[4 + 2 * r];
        }
    }
    const float* pw0 = (const float*)d_in[9];
    const float* pw1 = (const float*)d_in[10];
    const float* pw2 = (const float*)d_in[11];
    const float* bw0 = (const float*)d_in[12];
    const float* bw1 = (const float*)d_in[13];
    float* out = (float*)d_out;

    const int PB = (NE * 4 + 255) / 256;  // 1563 blocks, 4 threads per entity

    k_zero<<<512, 256>>>();
    k_deg<<<dim3(512, 3), 256>>>(ep);
    k_scan1<<<dim3(98, 6), 256>>>();
    k_scan2<<<1, 32>>>();
    k_scan3<<<dim3(98, 6), 256>>>();
    k_fill<<<dim3(512, 3), 256>>>(ep);

    for (int r = 0; r < 3; r++)
        k_pool16<<<dim3(PB, 2), 256>>>(ep.vals[r], r);
    k_entity<16><<<dim3(1024, 3), 256>>>(pw0);
    k_bnfin<<<1, 192>>>();
    k_bcastW<<<dim3(1024, 6), 256>>>(bw0, 0);

    for (int r = 0; r < 3; r++)
        k_pool64<<<dim3(PB, 2), 256>>>(r);
    k_entity<64><<<dim3(1024, 3), 256>>>(pw1);
    k_bnfin<<<1, 192>>>();
    k_bcastW<<<dim3(1024, 4), 256>>>(bw1, 1);

    k_pool64s3<<<dim3(PB, 2), 256>>>();
    k_out<<<1024, 256>>>(pw2, out);
}